// round 12
// baseline (speedup 1.0000x reference)
#include <cuda_runtime.h>
#include <cooperative_groups.h>
#include <math.h>

namespace cg = cooperative_groups;

// Problem constants (fixed shapes)
#define S_LEN 2048
#define B_SZ  64
#define H_DIM 1024
#define D_HALF 64
#define W_WIN 129            // 2*D+1
#define DCH   64             // d-chunk for GEMM partial
#define NDC   (H_DIM / DCH)  // 16
#define NT    512            // fused kernel threads (16 warps; reg cap 128)

// Scratch (allocation-free)
__device__ float g_dotp[NDC * B_SZ * H_DIM];   // [dc][b][h]  4 MB

// ---- packed f32x2 helpers (FFMA2: 2x fp32 FMA throughput, same rounding) ----
__device__ __forceinline__ unsigned long long pk2(float lo, float hi) {
    unsigned long long r;
    asm("mov.b64 %0, {%1, %2};" : "=l"(r) : "f"(lo), "f"(hi));
    return r;
}
__device__ __forceinline__ void fma2(unsigned long long& d,
                                     unsigned long long a, unsigned long long b) {
    asm("fma.rn.f32x2 %0, %1, %2, %0;" : "+l"(d) : "l"(a), "l"(b));
}
__device__ __forceinline__ void upk2(unsigned long long v, float& lo, float& hi) {
    asm("mov.b64 {%0, %1}, %2;" : "=f"(lo), "=f"(hi) : "l"(v));
}

// ---------------------------------------------------------------------------
// K1: partial GEMM via FFMA2.  dotp[dc][b][h] = sum_d hidden[b][d]*Wp_w[h][d]
// fp32 semantics preserved exactly: p feeds round() -> window center.
// ---------------------------------------------------------------------------
__global__ __launch_bounds__(256, 2)
void k_gemm_partial(const float* __restrict__ hidden,
                    const float* __restrict__ Wp_w) {
    const int h0 = blockIdx.x * 64;
    const int dc = blockIdx.y;
    const int d0 = dc * DCH;

    __shared__ float sh_ht[DCH][66];  // [d][b] padded (b contiguous)
    __shared__ float sh_w[DCH][65];   // [d][h] padded

    const int tid  = threadIdx.x;
    const int lane = tid & 31;
    const int warp = tid >> 5;

    for (int idx = tid; idx < 64 * 16; idx += 256) {
        int b  = idx >> 4;
        int dq = (idx & 15) << 2;
        float4 v = *reinterpret_cast<const float4*>(&hidden[b * H_DIM + d0 + dq]);
        sh_ht[dq + 0][b] = v.x; sh_ht[dq + 1][b] = v.y;
        sh_ht[dq + 2][b] = v.z; sh_ht[dq + 3][b] = v.w;
    }
    for (int idx = tid; idx < 64 * 16; idx += 256) {
        int h  = idx >> 4;
        int dq = (idx & 15) << 2;
        float4 v = *reinterpret_cast<const float4*>(&Wp_w[(size_t)(h0 + h) * H_DIM + d0 + dq]);
        sh_w[dq + 0][h] = v.x; sh_w[dq + 1][h] = v.y;
        sh_w[dq + 2][h] = v.z; sh_w[dq + 3][h] = v.w;
    }
    __syncthreads();

    const int hl = lane & 15;
    const int bl = ((lane >> 4) << 2) + (warp << 3);   // multiple of 4 -> LDS.64 aligned

    unsigned long long acc2[2][4] = {};
#pragma unroll 16
    for (int d = 0; d < DCH; ++d) {
        float wv0 = sh_w[d][hl];
        float wv1 = sh_w[d][hl + 16];
        float wv2 = sh_w[d][hl + 32];
        float wv3 = sh_w[d][hl + 48];
        unsigned long long wp0 = pk2(wv0, wv0);
        unsigned long long wp1 = pk2(wv1, wv1);
        unsigned long long wp2 = pk2(wv2, wv2);
        unsigned long long wp3 = pk2(wv3, wv3);
        unsigned long long h01 = *reinterpret_cast<const unsigned long long*>(&sh_ht[d][bl]);
        unsigned long long h23 = *reinterpret_cast<const unsigned long long*>(&sh_ht[d][bl + 2]);
        fma2(acc2[0][0], h01, wp0); fma2(acc2[0][1], h01, wp1);
        fma2(acc2[0][2], h01, wp2); fma2(acc2[0][3], h01, wp3);
        fma2(acc2[1][0], h23, wp0); fma2(acc2[1][1], h23, wp1);
        fma2(acc2[1][2], h23, wp2); fma2(acc2[1][3], h23, wp3);
    }

    float* outp = &g_dotp[(size_t)dc * (B_SZ * H_DIM)];
#pragma unroll
    for (int r = 0; r < 2; ++r) {
#pragma unroll
        for (int i = 0; i < 4; ++i) {
            float lo, hi;
            upk2(acc2[r][i], lo, hi);
            int h = h0 + hl + 16 * i;
            outp[(bl + 2 * r + 0) * H_DIM + h] = lo;
            outp[(bl + 2 * r + 1) * H_DIM + h] = hi;
        }
    }
}

// ---------------------------------------------------------------------------
// K2 (fused, clustered, flash-style, software-pipelined): 2 CTAs per b,
// 128 blocks, 512 threads. Depth-2 ping-pong: row w+16's loads issue before
// row w's compute, hiding DRAM latency behind the dot/softmax/ctx chain.
// ---------------------------------------------------------------------------
struct DynSmem {
    float4 ctxw[16][256];   // per-warp ctx accumulators     (64 KB)
    float4 ctx_comb[256];   // rank-combined unnormalized ctx (4 KB)
    float  hid[H_DIM];      // hidden row                     (4 KB)
    float  scores[W_WIN];   // raw scores (own half valid)
    float  m[16];
    float  l[16];
    float  ef[16];
    float  wred[16];
    float  part;
    float  p;
    int    c;
    float  Mrank;           // max of this rank's scores
    float  lrank;           // sum exp(sc - Mrank), this rank
};

__global__ __launch_bounds__(NT, 1) __cluster_dims__(2, 1, 1)
void k_attn_fused(const float* __restrict__ hidden,
                  const float* __restrict__ enc,
                  const float* __restrict__ Wp_b,
                  const float* __restrict__ vp_w,
                  const float* __restrict__ vp_b,
                  float* __restrict__ d_out) {
    cg::cluster_group cluster = cg::this_cluster();
    extern __shared__ __align__(16) char dsm_raw[];
    DynSmem* sm = reinterpret_cast<DynSmem*>(dsm_raw);

    const int b    = blockIdx.x >> 1;
    const int rank = blockIdx.x & 1;
    const int peer = rank ^ 1;
    const int tid  = threadIdx.x;
    const int lane = tid & 31;
    const int warp = tid >> 5;   // 0..15

    // stage hidden row
    for (int i = tid; i < H_DIM; i += NT) sm->hid[i] = hidden[b * H_DIM + i];

    // ---- phase 1: p partial over this rank's h-half ----
    {
        float local = 0.f;
        for (int h = tid; h < 512; h += NT) {
            const int hh = rank * 512 + h;
            float pa[NDC];
#pragma unroll
            for (int dc = 0; dc < NDC; ++dc)
                pa[dc] = g_dotp[dc * (B_SZ * H_DIM) + b * H_DIM + hh];
            float s = Wp_b[hh];
#pragma unroll
            for (int dc = 0; dc < NDC; ++dc) s += pa[dc];
            local += vp_w[hh] * tanhf(s);
        }
#pragma unroll
        for (int off = 16; off > 0; off >>= 1)
            local += __shfl_down_sync(0xffffffffu, local, off);
        if (lane == 0) sm->wred[warp] = local;
        __syncthreads();
        if (warp == 0) {
            float v = (lane < 16) ? sm->wred[lane] : 0.f;
#pragma unroll
            for (int off = 8; off > 0; off >>= 1)
                v += __shfl_down_sync(0xffffffffu, v, off);
            if (lane == 0) sm->part = v;
        }
    }
    cluster.sync();   // publish part to peer

    if (tid == 0) {
        const float* pp = (const float*)cluster.map_shared_rank((void*)&sm->part, peer);
        float tot = sm->part + *pp + vp_b[0];   // commutative: identical in both ranks
        float p = (float)S_LEN / (1.f + expf(-tot));   // exact expf: feeds round()
        sm->p = p;
        sm->c = (int)rintf(p);                  // round-half-even == jnp.round
    }
    __syncthreads();
    const int   c = sm->c;
    const float p = sm->p;
    const int wbeg = rank * 65;
    const int wend = rank ? W_WIN : 65;

    // ---- phase 2: pipelined flash pass ----
    {
        const float4* h4 = reinterpret_cast<const float4*>(sm->hid);

        float4 ctx[8];
#pragma unroll
        for (int k = 0; k < 8; ++k) ctx[k] = make_float4(0.f, 0.f, 0.f, 0.f);
        float m = -1e30f;
        float l = 0.f;

        auto load_row = [&](float4* e, int w) {
            const int s = c + w - D_HALF;
            if (s >= 0 && s < S_LEN) {
                const float4* p1 = reinterpret_cast<const float4*>(
                    enc + ((size_t)s * B_SZ + b) * H_DIM);
#pragma unroll
                for (int k = 0; k < 8; ++k) e[k] = p1[k * 32 + lane];   // batched LDG.128
            } else {
#pragma unroll
                for (int k = 0; k < 8; ++k) e[k] = make_float4(0.f, 0.f, 0.f, 0.f);
            }
        };

        auto compute_row = [&](const float4* e, int w) {
            float a0 = 0.f, a1 = 0.f;
#pragma unroll
            for (int k = 0; k < 8; ++k) {
                float4 hh = h4[k * 32 + lane];   // LDS (pipelined, not on crit path)
                a0 += e[k].x * hh.x + e[k].z * hh.z;
                a1 += e[k].y * hh.y + e[k].w * hh.w;
            }
            float v = a0 + a1;
#pragma unroll
            for (int off = 16; off > 0; off >>= 1)
                v += __shfl_xor_sync(0xffffffffu, v, off);   // lane-identical
            if (lane == 0) sm->scores[w] = v;

            float m_new = fmaxf(m, v);
            float scale = __expf(m - m_new);
            float ew    = __expf(v - m_new);
            float diff  = (float)(c + w - D_HALF) - p;
            float g     = __expf(-diff * diff * (1.f / 2048.f));   // stddev=D/2=32
            float cw    = ew * g;
            l = l * scale + ew;
#pragma unroll
            for (int k = 0; k < 8; ++k) {
                ctx[k].x = ctx[k].x * scale + cw * e[k].x;
                ctx[k].y = ctx[k].y * scale + cw * e[k].y;
                ctx[k].z = ctx[k].z * scale + cw * e[k].z;
                ctx[k].w = ctx[k].w * scale + cw * e[k].w;
            }
            m = m_new;
        };

        float4 eA[8], eB[8];
        int w = wbeg + warp;
        if (w < wend) load_row(eA, w);            // prologue
        for (; w < wend; w += 32) {
            const int w2 = w + 16;
            const bool okB = (w2 < wend);
            if (okB) load_row(eB, w2);            // prefetch B before compute A
            compute_row(eA, w);
            const int w3 = w + 32;
            if (w3 < wend) load_row(eA, w3);      // prefetch next A before compute B
            if (okB) compute_row(eB, w2);
        }

        // publish per-warp state
        if (lane == 0) { sm->m[warp] = m; sm->l[warp] = l; }
#pragma unroll
        for (int k = 0; k < 8; ++k) sm->ctxw[warp][k * 32 + lane] = ctx[k];
    }
    __syncthreads();

    // ---- combine 16 warps within the rank ----
    if (tid == 0) {
        float M = -1e30f;
#pragma unroll
        for (int w2 = 0; w2 < 16; ++w2) M = fmaxf(M, sm->m[w2]);
        float L = 0.f;
#pragma unroll
        for (int w2 = 0; w2 < 16; ++w2) {
            float f = expf(sm->m[w2] - M);
            sm->ef[w2] = f;
            L += sm->l[w2] * f;
        }
        sm->Mrank = M;
        sm->lrank = L;
    }
    __syncthreads();

    if (tid < 256) {
        float4 o = make_float4(0.f, 0.f, 0.f, 0.f);
#pragma unroll
        for (int w2 = 0; w2 < 16; ++w2) {
            float  f = sm->ef[w2];
            float4 t = sm->ctxw[w2][tid];
            o.x += f * t.x; o.y += f * t.y;
            o.z += f * t.z; o.w += f * t.w;
        }
        sm->ctx_comb[tid] = o;
    }
    cluster.sync();   // publish ctx_comb, Mrank, lrank, scores

    // ---- cross-rank combine + outputs ----
    {
        const DynSmem* ps = (const DynSmem*)cluster.map_shared_rank((void*)sm, peer);
        const float peerM = ps->Mrank;
        const float peerl = ps->lrank;
        const float Mg = fmaxf(sm->Mrank, peerM);
        const float e_own  = expf(sm->Mrank - Mg);
        const float e_peer = expf(peerM - Mg);
        const float L = sm->lrank * e_own + peerl * e_peer;
        const float invL = 1.f / L;

        // context: own h-half = own-rows ctx + peer-rows ctx, normalized
        if (tid < 128) {
            const int idx = rank * 128 + tid;
            float4 a = sm->ctx_comb[idx];
            float4 q = ps->ctx_comb[idx];     // DSMEM read
            float4 o;
            o.x = (a.x * e_own + q.x * e_peer) * invL;
            o.y = (a.y * e_own + q.y * e_peer) * invL;
            o.z = (a.z * e_own + q.z * e_peer) * invL;
            o.w = (a.w * e_own + q.w * e_peer) * invL;
            reinterpret_cast<float4*>(
                d_out + B_SZ * W_WIN + b * H_DIM + rank * 512)[tid] = o;
        }

        // attn output (rank 0 only): exp(sc - Mg)/L * gauss
        if (rank == 0 && tid < W_WIN) {
            float sc = (tid < 65) ? sm->scores[tid] : ps->scores[tid];
            float diff = (float)(c + tid - D_HALF) - p;
            float g = __expf(-diff * diff * (1.f / 2048.f));
            d_out[b * W_WIN + tid] = __expf(sc - Mg) * invL * g;
        }
    }

    cluster.sync();   // no CTA exits while peer may still read its DSMEM
}

// ---------------------------------------------------------------------------
extern "C" void kernel_launch(void* const* d_in, const int* in_sizes, int n_in,
                              void* d_out, int out_size) {
    // metadata order: t, hidden, encoder_outputs, Wp_w, Wp_b, vp_w, vp_b
    const float* hidden = (const float*)d_in[1];
    const float* enc    = (const float*)d_in[2];
    const float* Wp_w   = (const float*)d_in[3];
    const float* Wp_b   = (const float*)d_in[4];
    const float* vp_w   = (const float*)d_in[5];
    const float* vp_b   = (const float*)d_in[6];
    float* out = (float*)d_out;

    // sticky module state; idempotent (first set happens on the uncaptured
    // correctness call, so capture-time behavior is unchanged)
    cudaFuncSetAttribute(k_attn_fused,
                         cudaFuncAttributeMaxDynamicSharedMemorySize,
                         (int)sizeof(DynSmem));

    k_gemm_partial<<<dim3(16, 16), 256>>>(hidden, Wp_w);
    k_attn_fused<<<B_SZ * 2, NT, sizeof(DynSmem)>>>(hidden, enc, Wp_b, vp_w, vp_b, out);
}

// round 13
// speedup vs baseline: 1.1929x; 1.1929x over previous
#include <cuda_runtime.h>
#include <cooperative_groups.h>
#include <math.h>

namespace cg = cooperative_groups;

// Problem constants (fixed shapes)
#define S_LEN 2048
#define B_SZ  64
#define H_DIM 1024
#define D_HALF 64
#define W_WIN 129            // 2*D+1
#define DCH   64             // d-chunk for GEMM partial
#define NDC   (H_DIM / DCH)  // 16
#define NT    512            // fused kernel threads (16 warps; reg cap 128)

// Scratch (allocation-free)
__device__ float g_dotp[NDC * B_SZ * H_DIM];   // [dc][b][h]  4 MB

// ---- packed f32x2 helpers (FFMA2: 2x fp32 FMA throughput, same rounding) ----
__device__ __forceinline__ unsigned long long pk2(float lo, float hi) {
    unsigned long long r;
    asm("mov.b64 %0, {%1, %2};" : "=l"(r) : "f"(lo), "f"(hi));
    return r;
}
__device__ __forceinline__ void fma2(unsigned long long& d,
                                     unsigned long long a, unsigned long long b) {
    asm("fma.rn.f32x2 %0, %1, %2, %0;" : "+l"(d) : "l"(a), "l"(b));
}
__device__ __forceinline__ void upk2(unsigned long long v, float& lo, float& hi) {
    asm("mov.b64 {%0, %1}, %2;" : "=f"(lo), "=f"(hi) : "l"(v));
}

// ---------------------------------------------------------------------------
// K1: partial GEMM via FFMA2.  dotp[dc][b][h] = sum_d hidden[b][d]*Wp_w[h][d]
// fp32 semantics preserved exactly: p feeds round() -> window center.
// ---------------------------------------------------------------------------
__global__ __launch_bounds__(256, 2)
void k_gemm_partial(const float* __restrict__ hidden,
                    const float* __restrict__ Wp_w) {
    const int h0 = blockIdx.x * 64;
    const int dc = blockIdx.y;
    const int d0 = dc * DCH;

    __shared__ float sh_ht[DCH][66];  // [d][b] padded (b contiguous)
    __shared__ float sh_w[DCH][65];   // [d][h] padded

    const int tid  = threadIdx.x;
    const int lane = tid & 31;
    const int warp = tid >> 5;

    for (int idx = tid; idx < 64 * 16; idx += 256) {
        int b  = idx >> 4;
        int dq = (idx & 15) << 2;
        float4 v = *reinterpret_cast<const float4*>(&hidden[b * H_DIM + d0 + dq]);
        sh_ht[dq + 0][b] = v.x; sh_ht[dq + 1][b] = v.y;
        sh_ht[dq + 2][b] = v.z; sh_ht[dq + 3][b] = v.w;
    }
    for (int idx = tid; idx < 64 * 16; idx += 256) {
        int h  = idx >> 4;
        int dq = (idx & 15) << 2;
        float4 v = *reinterpret_cast<const float4*>(&Wp_w[(size_t)(h0 + h) * H_DIM + d0 + dq]);
        sh_w[dq + 0][h] = v.x; sh_w[dq + 1][h] = v.y;
        sh_w[dq + 2][h] = v.z; sh_w[dq + 3][h] = v.w;
    }
    __syncthreads();

    const int hl = lane & 15;
    const int bl = ((lane >> 4) << 2) + (warp << 3);   // multiple of 4 -> LDS.64 aligned

    unsigned long long acc2[2][4] = {};
#pragma unroll 16
    for (int d = 0; d < DCH; ++d) {
        float wv0 = sh_w[d][hl];
        float wv1 = sh_w[d][hl + 16];
        float wv2 = sh_w[d][hl + 32];
        float wv3 = sh_w[d][hl + 48];
        unsigned long long wp0 = pk2(wv0, wv0);
        unsigned long long wp1 = pk2(wv1, wv1);
        unsigned long long wp2 = pk2(wv2, wv2);
        unsigned long long wp3 = pk2(wv3, wv3);
        unsigned long long h01 = *reinterpret_cast<const unsigned long long*>(&sh_ht[d][bl]);
        unsigned long long h23 = *reinterpret_cast<const unsigned long long*>(&sh_ht[d][bl + 2]);
        fma2(acc2[0][0], h01, wp0); fma2(acc2[0][1], h01, wp1);
        fma2(acc2[0][2], h01, wp2); fma2(acc2[0][3], h01, wp3);
        fma2(acc2[1][0], h23, wp0); fma2(acc2[1][1], h23, wp1);
        fma2(acc2[1][2], h23, wp2); fma2(acc2[1][3], h23, wp3);
    }

    float* outp = &g_dotp[(size_t)dc * (B_SZ * H_DIM)];
#pragma unroll
    for (int r = 0; r < 2; ++r) {
#pragma unroll
        for (int i = 0; i < 4; ++i) {
            float lo, hi;
            upk2(acc2[r][i], lo, hi);
            int h = h0 + hl + 16 * i;
            outp[(bl + 2 * r + 0) * H_DIM + h] = lo;
            outp[(bl + 2 * r + 1) * H_DIM + h] = hi;
        }
    }
}

// ---------------------------------------------------------------------------
// K2 (fused, clustered, flash-style): 2 CTAs per b, 128 blocks, 512 threads.
// Single-buffer flash loop (R11 structure); per-row critical path shortened:
// __expf (MUFU), precomputed gaussian, warp-uniform rescale branch.
// ---------------------------------------------------------------------------
struct DynSmem {
    float4 ctxw[16][256];   // per-warp ctx accumulators     (64 KB)
    float4 ctx_comb[256];   // rank-combined unnormalized ctx (4 KB)
    float  hid[H_DIM];      // hidden row                     (4 KB)
    float  scores[W_WIN];   // raw scores (own half valid)
    float  gauss[W_WIN];    // gaussian positional weights
    float  m[16];
    float  l[16];
    float  ef[16];
    float  wred[16];
    float  part;
    float  p;
    int    c;
    float  Mrank;           // max of this rank's scores
    float  lrank;           // sum exp(sc - Mrank), this rank
};

__global__ __launch_bounds__(NT, 1) __cluster_dims__(2, 1, 1)
void k_attn_fused(const float* __restrict__ hidden,
                  const float* __restrict__ enc,
                  const float* __restrict__ Wp_b,
                  const float* __restrict__ vp_w,
                  const float* __restrict__ vp_b,
                  float* __restrict__ d_out) {
    cg::cluster_group cluster = cg::this_cluster();
    extern __shared__ __align__(16) char dsm_raw[];
    DynSmem* sm = reinterpret_cast<DynSmem*>(dsm_raw);

    const int b    = blockIdx.x >> 1;
    const int rank = blockIdx.x & 1;
    const int peer = rank ^ 1;
    const int tid  = threadIdx.x;
    const int lane = tid & 31;
    const int warp = tid >> 5;   // 0..15

    // stage hidden row
    for (int i = tid; i < H_DIM; i += NT) sm->hid[i] = hidden[b * H_DIM + i];

    // ---- phase 1: p partial over this rank's h-half ----
    {
        float local = 0.f;
        for (int h = tid; h < 512; h += NT) {
            const int hh = rank * 512 + h;
            float pa[NDC];
#pragma unroll
            for (int dc = 0; dc < NDC; ++dc)
                pa[dc] = g_dotp[dc * (B_SZ * H_DIM) + b * H_DIM + hh];
            float s = Wp_b[hh];
#pragma unroll
            for (int dc = 0; dc < NDC; ++dc) s += pa[dc];
            local += vp_w[hh] * tanhf(s);
        }
#pragma unroll
        for (int off = 16; off > 0; off >>= 1)
            local += __shfl_down_sync(0xffffffffu, local, off);
        if (lane == 0) sm->wred[warp] = local;
        __syncthreads();
        if (warp == 0) {
            float v = (lane < 16) ? sm->wred[lane] : 0.f;
#pragma unroll
            for (int off = 8; off > 0; off >>= 1)
                v += __shfl_down_sync(0xffffffffu, v, off);
            if (lane == 0) sm->part = v;
        }
    }
    cluster.sync();   // publish part to peer

    if (tid == 0) {
        const float* pp = (const float*)cluster.map_shared_rank((void*)&sm->part, peer);
        float tot = sm->part + *pp + vp_b[0];   // commutative: identical in both ranks
        float p = (float)S_LEN / (1.f + expf(-tot));   // exact expf: feeds round()
        sm->p = p;
        sm->c = (int)rintf(p);                  // round-half-even == jnp.round
    }
    __syncthreads();
    const int   c = sm->c;
    const float p = sm->p;
    const int wbeg = rank * 65;
    const int wend = rank ? W_WIN : 65;

    // precompute gaussian weights (removes one exp from the per-row chain)
    if (tid < W_WIN) {
        float diff = (float)(c + tid - D_HALF) - p;
        sm->gauss[tid] = __expf(-diff * diff * (1.f / 2048.f));   // stddev=D/2=32
    }
    __syncthreads();

    // ---- phase 2: flash pass (single buffer, short per-row chain) ----
    {
        const float4* h4 = reinterpret_cast<const float4*>(sm->hid);
        float4 hh[8];
#pragma unroll
        for (int k = 0; k < 8; ++k) hh[k] = h4[k * 32 + lane];   // once, in regs

        float4 ctx[8];
#pragma unroll
        for (int k = 0; k < 8; ++k) ctx[k] = make_float4(0.f, 0.f, 0.f, 0.f);
        float m = -1e30f;
        float l = 0.f;

        for (int w = wbeg + warp; w < wend; w += 16) {
            const int s = c + w - D_HALF;
            const bool ok = (s >= 0) && (s < S_LEN);

            float4 e[8];
            if (ok) {
                const float4* p1 = reinterpret_cast<const float4*>(
                    enc + ((size_t)s * B_SZ + b) * H_DIM);
#pragma unroll
                for (int k = 0; k < 8; ++k) e[k] = p1[k * 32 + lane];   // batched LDG.128
            } else {
#pragma unroll
                for (int k = 0; k < 8; ++k) e[k] = make_float4(0.f, 0.f, 0.f, 0.f);
            }

            // dot(hidden, row) -> v on all lanes (butterfly: lane-identical)
            float a0 = 0.f, a1 = 0.f;
#pragma unroll
            for (int k = 0; k < 8; ++k) {
                a0 += e[k].x * hh[k].x + e[k].z * hh[k].z;
                a1 += e[k].y * hh[k].y + e[k].w * hh[k].w;
            }
            float v = a0 + a1;
#pragma unroll
            for (int off = 16; off > 0; off >>= 1)
                v += __shfl_xor_sync(0xffffffffu, v, off);

            if (lane == 0) sm->scores[w] = v;
            float g = sm->gauss[w];   // broadcast LDS, off critical path

            // warp-uniform rescale (v lane-identical -> no divergence)
            if (v > m) {
                float scale = __expf(m - v);
                l *= scale;
#pragma unroll
                for (int k = 0; k < 8; ++k) {
                    ctx[k].x *= scale; ctx[k].y *= scale;
                    ctx[k].z *= scale; ctx[k].w *= scale;
                }
                m = v;
            }
            float ew = __expf(v - m);
            l += ew;
            float cw = ew * g;
#pragma unroll
            for (int k = 0; k < 8; ++k) {
                ctx[k].x += cw * e[k].x; ctx[k].y += cw * e[k].y;
                ctx[k].z += cw * e[k].z; ctx[k].w += cw * e[k].w;
            }
        }

        // publish per-warp state
        if (lane == 0) { sm->m[warp] = m; sm->l[warp] = l; }
#pragma unroll
        for (int k = 0; k < 8; ++k) sm->ctxw[warp][k * 32 + lane] = ctx[k];
    }
    __syncthreads();

    // ---- combine 16 warps within the rank ----
    if (tid == 0) {
        float M = -1e30f;
#pragma unroll
        for (int w2 = 0; w2 < 16; ++w2) M = fmaxf(M, sm->m[w2]);
        float L = 0.f;
#pragma unroll
        for (int w2 = 0; w2 < 16; ++w2) {
            float f = expf(sm->m[w2] - M);
            sm->ef[w2] = f;
            L += sm->l[w2] * f;
        }
        sm->Mrank = M;
        sm->lrank = L;
    }
    __syncthreads();

    if (tid < 256) {
        float4 o = make_float4(0.f, 0.f, 0.f, 0.f);
#pragma unroll
        for (int w2 = 0; w2 < 16; ++w2) {
            float  f = sm->ef[w2];
            float4 t = sm->ctxw[w2][tid];
            o.x += f * t.x; o.y += f * t.y;
            o.z += f * t.z; o.w += f * t.w;
        }
        sm->ctx_comb[tid] = o;
    }
    cluster.sync();   // publish ctx_comb, Mrank, lrank, scores

    // ---- cross-rank combine + outputs ----
    {
        const DynSmem* ps = (const DynSmem*)cluster.map_shared_rank((void*)sm, peer);
        const float peerM = ps->Mrank;
        const float peerl = ps->lrank;
        const float Mg = fmaxf(sm->Mrank, peerM);
        const float e_own  = expf(sm->Mrank - Mg);
        const float e_peer = expf(peerM - Mg);
        const float L = sm->lrank * e_own + peerl * e_peer;
        const float invL = 1.f / L;

        // context: own h-half = own-rows ctx + peer-rows ctx, normalized
        if (tid < 128) {
            const int idx = rank * 128 + tid;
            float4 a = sm->ctx_comb[idx];
            float4 q = ps->ctx_comb[idx];     // DSMEM read
            float4 o;
            o.x = (a.x * e_own + q.x * e_peer) * invL;
            o.y = (a.y * e_own + q.y * e_peer) * invL;
            o.z = (a.z * e_own + q.z * e_peer) * invL;
            o.w = (a.w * e_own + q.w * e_peer) * invL;
            reinterpret_cast<float4*>(
                d_out + B_SZ * W_WIN + b * H_DIM + rank * 512)[tid] = o;
        }

        // attn output (rank 0 only): exp(sc - Mg)/L * gauss
        if (rank == 0 && tid < W_WIN) {
            float sc = (tid < 65) ? sm->scores[tid] : ps->scores[tid];
            d_out[b * W_WIN + tid] = __expf(sc - Mg) * invL * sm->gauss[tid];
        }
    }

    cluster.sync();   // no CTA exits while peer may still read its DSMEM
}

// ---------------------------------------------------------------------------
extern "C" void kernel_launch(void* const* d_in, const int* in_sizes, int n_in,
                              void* d_out, int out_size) {
    // metadata order: t, hidden, encoder_outputs, Wp_w, Wp_b, vp_w, vp_b
    const float* hidden = (const float*)d_in[1];
    const float* enc    = (const float*)d_in[2];
    const float* Wp_w   = (const float*)d_in[3];
    const float* Wp_b   = (const float*)d_in[4];
    const float* vp_w   = (const float*)d_in[5];
    const float* vp_b   = (const float*)d_in[6];
    float* out = (float*)d_out;

    // sticky module state; idempotent (first set happens on the uncaptured
    // correctness call, so capture-time behavior is unchanged)
    cudaFuncSetAttribute(k_attn_fused,
                         cudaFuncAttributeMaxDynamicSharedMemorySize,
                         (int)sizeof(DynSmem));

    k_gemm_partial<<<dim3(16, 16), 256>>>(hidden, Wp_w);
    k_attn_fused<<<B_SZ * 2, NT, sizeof(DynSmem)>>>(hidden, enc, Wp_b, vp_w, vp_b, out);
}